// round 1
// baseline (speedup 1.0000x reference)
#include <cuda_runtime.h>
#include <math.h>

#define NE 100000
#define NR 10
#define EDIM 128
#define HID 256
#define NREG 2000
#define NKG 600000
#define NMP_ENT 40000
#define NMP_REL 5
#define NMP_E 300000
#define NB 1024
#define ATT 128

#define KMAIN (NR * EDIM + EDIM)     /* 1408 */
#define KMP (NMP_REL * EDIM + EDIM)  /* 768  */

// ---------------- scratch (device globals; no runtime allocation) ----------
__device__ float g_agg[(size_t)NE * KMAIN];       // 563 MB, reused for metapaths
__device__ float g_E[(size_t)NE * EDIM];          // tanh(rgcn) output
__device__ float g_ET[(size_t)EDIM * NE];         // E transposed
__device__ float g_Bmain[KMAIN * EDIM];           // [W_0..W_9 ; Wroot]
__device__ float g_Bmp[2][KMP * HID];             // per-metapath [W ; Wroot]
__device__ float g_x[NB * EDIM];                  // E[h] * R[r]
__device__ float g_sem[2][NREG * HID];            // metapath outputs (relu)
__device__ float g_w[2];                          // semantic-attention logits

// ---------------- stage 1: build concatenated A operand --------------------
// row n = [ zeros(1280) | E_weight[n] ]  (edges scattered into first 1280)
__global__ void init_agg_main(const float* __restrict__ X) {
    int n = blockIdx.x;
    float4* row = (float4*)(g_agg + (size_t)n * KMAIN);
    const float4* xr = (const float4*)(X + (size_t)n * EDIM);
    const float4 z = make_float4(0.f, 0.f, 0.f, 0.f);
    for (int j = threadIdx.x; j < KMAIN / 4; j += blockDim.x)
        row[j] = (j < (KMAIN - EDIM) / 4) ? z : xr[j - (KMAIN - EDIM) / 4];
}

__global__ void build_Bmain(const float* __restrict__ W, const float* __restrict__ Wroot) {
    int i = blockIdx.x * blockDim.x + threadIdx.x;
    const int n1 = NR * EDIM * EDIM;
    if (i < n1) g_Bmain[i] = W[i];
    else if (i < n1 + EDIM * EDIM) g_Bmain[i] = Wroot[i - n1];
}

// one warp per edge: agg[dst, etype, :] += X[src, :]
__global__ void scatter_main(const int* __restrict__ ei, const int* __restrict__ et,
                             const float* __restrict__ X) {
    int w = (blockIdx.x * blockDim.x + threadIdx.x) >> 5;
    int lane = threadIdx.x & 31;
    if (w >= NKG) return;
    int src = ei[w];
    int dst = ei[NKG + w];
    int r = et[w];
    const float4 v = ((const float4*)(X + (size_t)src * EDIM))[lane];
    float* base = g_agg + (size_t)dst * KMAIN + r * EDIM + lane * 4;
    atomicAdd(base + 0, v.x);
    atomicAdd(base + 1, v.y);
    atomicAdd(base + 2, v.z);
    atomicAdd(base + 3, v.w);
}

// ---------------- generic SGEMM: C = act(A[M,K] * B[K,N] + bias) -----------
// BM=BN=128, BK=16, 256 threads, 8x8 micro-tile, float4 LDS
__global__ __launch_bounds__(256, 2)
void sgemm128(const float* __restrict__ A, const float* __restrict__ Bm,
              const float* __restrict__ bias, float* __restrict__ C,
              int M, int N, int K, int act) {
    __shared__ float As[16][132];
    __shared__ float Bs[16][128];
    const int bm = blockIdx.x * 128;
    const int bn = blockIdx.y * 128;
    const int tid = threadIdx.x;
    const int tm = tid >> 4;  // 0..15 : rows tm*8..tm*8+7
    const int tn = tid & 15;  // 0..15 : cols tn*8..tn*8+7

    float acc[8][8];
#pragma unroll
    for (int i = 0; i < 8; i++)
#pragma unroll
        for (int j = 0; j < 8; j++) acc[i][j] = 0.f;

    for (int k0 = 0; k0 < K; k0 += 16) {
#pragma unroll
        for (int l = 0; l < 2; l++) {               // A tile, stored transposed
            int idx = tid + l * 256;                // 512 float4 slots
            int m = idx >> 2, j = idx & 3;
            int gr = bm + m;
            float4 v = make_float4(0.f, 0.f, 0.f, 0.f);
            if (gr < M) v = *(const float4*)&A[(size_t)gr * K + k0 + j * 4];
            As[j * 4 + 0][m] = v.x;
            As[j * 4 + 1][m] = v.y;
            As[j * 4 + 2][m] = v.z;
            As[j * 4 + 3][m] = v.w;
        }
#pragma unroll
        for (int l = 0; l < 2; l++) {               // B tile
            int idx = tid + l * 256;
            int kk = idx >> 5, o4 = idx & 31;
            int gc = bn + o4 * 4;
            float4 v = make_float4(0.f, 0.f, 0.f, 0.f);
            if (gc < N) v = *(const float4*)&Bm[(size_t)(k0 + kk) * N + gc];
            *(float4*)&Bs[kk][o4 * 4] = v;
        }
        __syncthreads();
#pragma unroll
        for (int kk = 0; kk < 16; kk++) {
            float a[8], b[8];
            *(float4*)&a[0] = *(const float4*)&As[kk][tm * 8];
            *(float4*)&a[4] = *(const float4*)&As[kk][tm * 8 + 4];
            *(float4*)&b[0] = *(const float4*)&Bs[kk][tn * 8];
            *(float4*)&b[4] = *(const float4*)&Bs[kk][tn * 8 + 4];
#pragma unroll
            for (int i = 0; i < 8; i++)
#pragma unroll
                for (int j = 0; j < 8; j++) acc[i][j] = fmaf(a[i], b[j], acc[i][j]);
        }
        __syncthreads();
    }

    float bcol[8];
#pragma unroll
    for (int j = 0; j < 8; j++) {
        int gc = bn + tn * 8 + j;
        bcol[j] = (bias != nullptr && gc < N) ? bias[gc] : 0.f;
    }
#pragma unroll
    for (int i = 0; i < 8; i++) {
        int gr = bm + tm * 8 + i;
        if (gr >= M) continue;
#pragma unroll
        for (int j4 = 0; j4 < 2; j4++) {
            int gc = bn + tn * 8 + j4 * 4;
            if (gc >= N) continue;  // N % 4 == 0 for all call sites
            float4 v;
            float* vv = (float*)&v;
#pragma unroll
            for (int c = 0; c < 4; c++) {
                float t = acc[i][j4 * 4 + c] + bcol[j4 * 4 + c];
                if (act == 1) t = tanhf(t);
                else if (act == 2) t = fmaxf(t, 0.f);
                vv[c] = t;
            }
            *(float4*)&C[(size_t)gr * N + gc] = v;
        }
    }
}

// ---------------- stage 2: KGE scoring --------------------------------------
__global__ void transposeE() {
    __shared__ float t[32][33];
    int n0 = blockIdx.x * 32;
    int c0 = blockIdx.y * 32;
    int tx = threadIdx.x, ty = threadIdx.y;
    t[ty][tx] = g_E[(size_t)(n0 + ty) * EDIM + c0 + tx];
    __syncthreads();
    g_ET[(size_t)(c0 + ty) * NE + n0 + tx] = t[tx][ty];
}

__global__ void build_x(const int* __restrict__ h_idx, const int* __restrict__ r_idx,
                        const float* __restrict__ R) {
    int b = blockIdx.x, i = threadIdx.x;
    g_x[b * EDIM + i] = g_E[(size_t)h_idx[b] * EDIM + i] * R[(size_t)r_idx[b] * EDIM + i];
}

// ---------------- stage 3: metapath RGCNs (only dst < NREG matters) --------
__global__ void init_mp(int mp, const int* __restrict__ eids) {
    int n = blockIdx.x;  // < NREG
    float4* row = (float4*)(g_agg + (size_t)mp * NREG * KMP + (size_t)n * KMP);
    const float4* er = (const float4*)(g_E + (size_t)eids[n] * EDIM);
    const float4 z = make_float4(0.f, 0.f, 0.f, 0.f);
    for (int j = threadIdx.x; j < KMP / 4; j += blockDim.x)
        row[j] = (j < (KMP - EDIM) / 4) ? z : er[j - (KMP - EDIM) / 4];
    if (blockIdx.x == 0 && threadIdx.x < 2) g_w[threadIdx.x] = 0.f;
}

__global__ void build_Bmp(int mp, const float* __restrict__ W, const float* __restrict__ Wroot) {
    int i = blockIdx.x * blockDim.x + threadIdx.x;
    const int n1 = NMP_REL * EDIM * HID;
    if (i < n1) g_Bmp[mp][i] = W[i];
    else if (i < n1 + EDIM * HID) g_Bmp[mp][i] = Wroot[i - n1];
}

__global__ void scatter_mp(int mp, const int* __restrict__ ei, const int* __restrict__ et,
                           const int* __restrict__ eids) {
    int w = (blockIdx.x * blockDim.x + threadIdx.x) >> 5;
    int lane = threadIdx.x & 31;
    if (w >= NMP_E) return;
    int dst = ei[NMP_E + w];
    if (dst >= NREG) return;  // output is sliced [:NREG] after the conv
    int src = ei[w];
    int r = et[w];
    const float4 v = ((const float4*)(g_E + (size_t)eids[src] * EDIM))[lane];
    float* base = g_agg + (size_t)mp * NREG * KMP + (size_t)dst * KMP + r * EDIM + lane * 4;
    atomicAdd(base + 0, v.x);
    atomicAdd(base + 1, v.y);
    atomicAdd(base + 2, v.z);
    atomicAdd(base + 3, v.w);
}

// ---------------- stage 4: semantic attention + prediction head -------------
__global__ void attn(const float* __restrict__ w1, const float* __restrict__ b1,
                     const float* __restrict__ w2) {
    int n = blockIdx.x, m = blockIdx.y, tid = threadIdx.x;  // 128 threads
    __shared__ float z[HID];
    __shared__ float red[ATT];
    const float* zp = &g_sem[m][(size_t)n * HID];
    z[tid] = zp[tid];
    z[tid + 128] = zp[tid + 128];
    __syncthreads();
    float acc = b1[tid];
#pragma unroll 8
    for (int k = 0; k < HID; k++) acc = fmaf(z[k], w1[k * ATT + tid], acc);
    red[tid] = tanhf(acc) * w2[tid];
    __syncthreads();
    for (int s = 64; s > 0; s >>= 1) {
        if (tid < s) red[tid] += red[tid + s];
        __syncthreads();
    }
    if (tid == 0) atomicAdd(&g_w[m], red[0] * (1.0f / NREG));
}

__global__ void finalk(const float* __restrict__ predW, const float* __restrict__ predb,
                       float* __restrict__ out) {
    int n = blockIdx.x, tid = threadIdx.x;  // 128 threads
    __shared__ float h[HID];
    float w0 = g_w[0], w1v = g_w[1];
    float mx = fmaxf(w0, w1v);
    float e0 = expf(w0 - mx), e1 = expf(w1v - mx);
    float inv = 1.f / (e0 + e1);
    float b0 = e0 * inv, b1 = e1 * inv;
    h[tid] = b0 * g_sem[0][(size_t)n * HID + tid] + b1 * g_sem[1][(size_t)n * HID + tid];
    h[tid + 128] =
        b0 * g_sem[0][(size_t)n * HID + tid + 128] + b1 * g_sem[1][(size_t)n * HID + tid + 128];
    __syncthreads();
    float acc = predb[tid] + g_E[(size_t)n * EDIM + tid];
#pragma unroll 8
    for (int k = 0; k < HID; k++) acc = fmaf(h[k], predW[k * EDIM + tid], acc);
    out[(size_t)n * EDIM + tid] = acc;
}

// ---------------- launch ----------------------------------------------------
extern "C" void kernel_launch(void* const* d_in, const int* in_sizes, int n_in,
                              void* d_out, int out_size) {
    const float* E_weight = (const float*)d_in[0];
    const float* R_weight = (const float*)d_in[1];
    const float* rgcn_W = (const float*)d_in[2];
    const float* rgcn_Wroot = (const float*)d_in[3];
    const float* rgcn_b = (const float*)d_in[4];
    const float* mp0_W = (const float*)d_in[5];
    const float* mp0_Wroot = (const float*)d_in[6];
    const float* mp0_b = (const float*)d_in[7];
    const float* mp1_W = (const float*)d_in[8];
    const float* mp1_Wroot = (const float*)d_in[9];
    const float* mp1_b = (const float*)d_in[10];
    const float* sa_w1 = (const float*)d_in[11];
    const float* sa_b1 = (const float*)d_in[12];
    const float* sa_w2 = (const float*)d_in[13];
    const float* pred_W = (const float*)d_in[14];
    const float* pred_b = (const float*)d_in[15];
    const int* h_idx = (const int*)d_in[16];
    const int* r_idx = (const int*)d_in[17];
    const int* edge_index = (const int*)d_in[18];
    const int* edge_type = (const int*)d_in[19];
    const int* mp0_ei = (const int*)d_in[20];
    const int* mp0_et = (const int*)d_in[21];
    const int* mp0_eids = (const int*)d_in[22];
    const int* mp1_ei = (const int*)d_in[23];
    const int* mp1_et = (const int*)d_in[24];
    const int* mp1_eids = (const int*)d_in[25];
    float* out = (float*)d_out;  // [E_reg 2000*128 | pred 1024*100000]

    float *pagg, *pE, *pET, *pBmain, *pBmp, *px, *psem;
    cudaGetSymbolAddress((void**)&pagg, g_agg);
    cudaGetSymbolAddress((void**)&pE, g_E);
    cudaGetSymbolAddress((void**)&pET, g_ET);
    cudaGetSymbolAddress((void**)&pBmain, g_Bmain);
    cudaGetSymbolAddress((void**)&pBmp, g_Bmp);
    cudaGetSymbolAddress((void**)&px, g_x);
    cudaGetSymbolAddress((void**)&psem, g_sem);

    // main RGCN: E = tanh([agg | X] @ [W ; Wroot] + b)
    init_agg_main<<<NE, 128>>>(E_weight);
    build_Bmain<<<(KMAIN * EDIM + 255) / 256, 256>>>(rgcn_W, rgcn_Wroot);
    scatter_main<<<NKG / 8, 256>>>(edge_index, edge_type, E_weight);
    sgemm128<<<dim3((NE + 127) / 128, 1), 256>>>(pagg, pBmain, rgcn_b, pE, NE, EDIM, KMAIN, 1);

    // KGE pred = (E[h]*R[r]) @ E^T
    transposeE<<<dim3(NE / 32, EDIM / 32), dim3(32, 32)>>>();
    build_x<<<NB, EDIM>>>(h_idx, r_idx, R_weight);
    sgemm128<<<dim3(NB / 128, (NE + 127) / 128), 256>>>(px, pET, nullptr, out + NREG * EDIM,
                                                        NB, NE, EDIM, 0);

    // metapath RGCNs (rows < NREG only) + relu
    init_mp<<<NREG, 128>>>(0, mp0_eids);
    init_mp<<<NREG, 128>>>(1, mp1_eids);
    build_Bmp<<<(KMP * HID + 255) / 256, 256>>>(0, mp0_W, mp0_Wroot);
    build_Bmp<<<(KMP * HID + 255) / 256, 256>>>(1, mp1_W, mp1_Wroot);
    scatter_mp<<<NMP_E / 8, 256>>>(0, mp0_ei, mp0_et, mp0_eids);
    scatter_mp<<<NMP_E / 8, 256>>>(1, mp1_ei, mp1_et, mp1_eids);
    sgemm128<<<dim3((NREG + 127) / 128, HID / 128), 256>>>(pagg, pBmp, mp0_b, psem,
                                                           NREG, HID, KMP, 2);
    sgemm128<<<dim3((NREG + 127) / 128, HID / 128), 256>>>(
        pagg + (size_t)NREG * KMP, pBmp + (size_t)KMP * HID, mp1_b,
        psem + (size_t)NREG * HID, NREG, HID, KMP, 2);

    // semantic attention + prediction head
    attn<<<dim3(NREG, 2), ATT>>>(sa_w1, sa_b1, sa_w2);
    finalk<<<NREG, EDIM>>>(pred_W, pred_b, out);
}

// round 2
// speedup vs baseline: 2.1726x; 2.1726x over previous
#include <cuda_runtime.h>
#include <math.h>

#define NE 100000
#define NR 10
#define EDIM 128
#define HID 256
#define NREG 2000
#define NKG 600000
#define NMP_REL 5
#define NMP_E 300000
#define NB 1024
#define ATT 128

#define NMAIN (NR * EDIM + EDIM)    /* 1408: GEMM-1 N dim (10 rel blocks + root) */
#define KMP (NMP_REL * EDIM + EDIM) /* 768 */

// ---------------- scratch ----------------------------------------------------
__device__ float g_Y[(size_t)NE * NMAIN];   // Y = X@Bcat; root cols double as accumulator; reused for mp agg
__device__ float g_E[(size_t)NE * EDIM];
__device__ float g_ET[(size_t)EDIM * NE];
__device__ float g_Bmain[EDIM * NMAIN];
__device__ float g_Bmp[2][KMP * HID];
__device__ float g_x[NB * EDIM];
__device__ float g_sem[2][NREG * HID];
__device__ float g_w[2];

// ---------------- primitives -------------------------------------------------
__device__ __forceinline__ float cvt_tf32(float x) {
    unsigned u;
    asm("cvt.rna.tf32.f32 %0, %1;" : "=r"(u) : "f"(x));
    return __uint_as_float(u);
}
__device__ __forceinline__ float4 cvt_tf32_4(float4 v) {
    return make_float4(cvt_tf32(v.x), cvt_tf32(v.y), cvt_tf32(v.z), cvt_tf32(v.w));
}
__device__ __forceinline__ void red_add_v4(float* addr, float4 v) {
    asm volatile("red.global.add.v4.f32 [%0], {%1, %2, %3, %4};"
                 :: "l"(addr), "f"(v.x), "f"(v.y), "f"(v.z), "f"(v.w) : "memory");
}
__device__ __forceinline__ void mma8(float* c, const unsigned* a, const unsigned* b) {
    asm volatile(
        "mma.sync.aligned.m16n8k8.row.col.f32.tf32.tf32.f32 "
        "{%0,%1,%2,%3}, {%4,%5,%6,%7}, {%8,%9}, {%0,%1,%2,%3};"
        : "+f"(c[0]), "+f"(c[1]), "+f"(c[2]), "+f"(c[3])
        : "r"(a[0]), "r"(a[1]), "r"(a[2]), "r"(a[3]), "r"(b[0]), "r"(b[1]));
}

// ---------------- tf32 tensor-core GEMM: C = act(A[M,K]@B[K,N] + bias) -------
// BM=BN=128, BK=16, 256 thr (8 warps, 4x2), warp tile 32x64, m16n8k8
__global__ __launch_bounds__(256)
void gemm_tf32(const float* __restrict__ A, int lda,
               const float* __restrict__ B, int ldb,
               const float* __restrict__ bias, float* __restrict__ C, int ldc,
               int M, int N, int K, int act) {
    __shared__ float As[2][128][20];   // [m][k], stride 20 -> conflict-free frag loads
    __shared__ float Bs[2][16][136];   // [k][n], stride 136 -> conflict-free frag loads
    const int bm = blockIdx.x * 128;
    const int bn = blockIdx.y * 128;
    const int tid = threadIdx.x;
    const int lane = tid & 31;
    const int warp = tid >> 5;
    const int g = lane >> 2, t = lane & 3;
    const int wm = (warp >> 1) * 32;
    const int wn = (warp & 1) * 64;

    float c[2][8][4];
#pragma unroll
    for (int i = 0; i < 2; i++)
#pragma unroll
        for (int j = 0; j < 8; j++)
#pragma unroll
            for (int l = 0; l < 4; l++) c[i][j][l] = 0.f;

    float4 ar[2], br[2];
    const float4 z4 = make_float4(0.f, 0.f, 0.f, 0.f);

    auto ldg = [&](int k0) {
#pragma unroll
        for (int l = 0; l < 2; l++) {
            int e = tid + l * 256;
            int m = e >> 2, k4 = (e & 3) * 4;
            int gm = bm + m;
            ar[l] = (gm < M) ? *(const float4*)&A[(size_t)gm * lda + k0 + k4] : z4;
            int kr = e >> 5, nc = (e & 31) * 4;
            int gc = bn + nc;
            br[l] = (gc < N) ? *(const float4*)&B[(size_t)(k0 + kr) * ldb + gc] : z4;
        }
    };
    auto sts = [&](int buf) {
#pragma unroll
        for (int l = 0; l < 2; l++) {
            int e = tid + l * 256;
            int m = e >> 2, k4 = (e & 3) * 4;
            *(float4*)&As[buf][m][k4] = cvt_tf32_4(ar[l]);
            int kr = e >> 5, nc = (e & 31) * 4;
            *(float4*)&Bs[buf][kr][nc] = cvt_tf32_4(br[l]);
        }
    };
    auto compute = [&](int buf) {
#pragma unroll
        for (int kk = 0; kk < 2; kk++) {
            const int kb = kk * 8;
            unsigned a[2][4], b[8][2];
#pragma unroll
            for (int mt = 0; mt < 2; mt++) {
                int row = wm + mt * 16 + g;
                a[mt][0] = __float_as_uint(As[buf][row][kb + t]);
                a[mt][1] = __float_as_uint(As[buf][row + 8][kb + t]);
                a[mt][2] = __float_as_uint(As[buf][row][kb + t + 4]);
                a[mt][3] = __float_as_uint(As[buf][row + 8][kb + t + 4]);
            }
#pragma unroll
            for (int nt = 0; nt < 8; nt++) {
                int col = wn + nt * 8 + g;
                b[nt][0] = __float_as_uint(Bs[buf][kb + t][col]);
                b[nt][1] = __float_as_uint(Bs[buf][kb + t + 4][col]);
            }
#pragma unroll
            for (int mt = 0; mt < 2; mt++)
#pragma unroll
                for (int nt = 0; nt < 8; nt++) mma8(c[mt][nt], a[mt], b[nt]);
        }
    };

    const int iters = K >> 4;   // K % 16 == 0 at every call site
    ldg(0);
    sts(0);
    __syncthreads();
    for (int it = 0; it < iters; it++) {
        int buf = it & 1;
        if (it + 1 < iters) ldg((it + 1) << 4);
        compute(buf);
        if (it + 1 < iters) sts(buf ^ 1);
        __syncthreads();
    }

#pragma unroll
    for (int mt = 0; mt < 2; mt++) {
#pragma unroll
        for (int h = 0; h < 2; h++) {
            int row = bm + wm + mt * 16 + g + h * 8;
            if (row >= M) continue;
#pragma unroll
            for (int nt = 0; nt < 8; nt++) {
                int col = bn + wn + nt * 8 + 2 * t;
                if (col >= N) continue;
                float v0 = c[mt][nt][h * 2 + 0];
                float v1 = c[mt][nt][h * 2 + 1];
                if (bias) { v0 += bias[col]; v1 += bias[col + 1]; }
                if (act == 1) { v0 = tanhf(v0); v1 = tanhf(v1); }
                else if (act == 2) { v0 = fmaxf(v0, 0.f); v1 = fmaxf(v1, 0.f); }
                *(float2*)&C[(size_t)row * ldc + col] = make_float2(v0, v1);
            }
        }
    }
}

// ---------------- stage 1: main RGCN -----------------------------------------
__global__ void build_Bmain(const float* __restrict__ W, const float* __restrict__ Wroot) {
    int i = blockIdx.x * blockDim.x + threadIdx.x;  // over 128*1408
    if (i >= EDIM * NMAIN) return;
    int k = i / NMAIN, n = i - k * NMAIN;
    int r = n >> 7, o = n & 127;
    g_Bmain[i] = (r < NR) ? W[((size_t)r * EDIM + k) * EDIM + o] : Wroot[k * EDIM + o];
}

// warp per edge: Y[dst, root-block] += Y[src, block etype]
__global__ void scatter_main(const int* __restrict__ ei, const int* __restrict__ et) {
    int w = (blockIdx.x * blockDim.x + threadIdx.x) >> 5;
    int lane = threadIdx.x & 31;
    if (w >= NKG) return;
    int src = ei[w], dst = ei[NKG + w], r = et[w];
    float4 v = *(const float4*)(g_Y + (size_t)src * NMAIN + r * EDIM + lane * 4);
    red_add_v4(g_Y + (size_t)dst * NMAIN + NR * EDIM + lane * 4, v);
}

__global__ void tanh_root(const float* __restrict__ b) {
    int i = blockIdx.x * blockDim.x + threadIdx.x;  // float4 units
    if (i >= NE * (EDIM / 4)) return;
    int n = i >> 5, j = (i & 31) * 4;
    float4 v = *(const float4*)&g_Y[(size_t)n * NMAIN + NR * EDIM + j];
    float4 bb = *(const float4*)&b[j];
    v.x = tanhf(v.x + bb.x);
    v.y = tanhf(v.y + bb.y);
    v.z = tanhf(v.z + bb.z);
    v.w = tanhf(v.w + bb.w);
    *(float4*)&g_E[(size_t)n * EDIM + j] = v;
}

// ---------------- stage 2: KGE scoring ---------------------------------------
__global__ void transposeE() {
    __shared__ float tbuf[32][33];
    int n0 = blockIdx.x * 32;
    int c0 = blockIdx.y * 32;
    int tx = threadIdx.x, ty = threadIdx.y;
    tbuf[ty][tx] = g_E[(size_t)(n0 + ty) * EDIM + c0 + tx];
    __syncthreads();
    g_ET[(size_t)(c0 + ty) * NE + n0 + tx] = tbuf[tx][ty];
}

__global__ void build_x(const int* __restrict__ h_idx, const int* __restrict__ r_idx,
                        const float* __restrict__ R) {
    int b = blockIdx.x, i = threadIdx.x;
    g_x[b * EDIM + i] = g_E[(size_t)h_idx[b] * EDIM + i] * R[(size_t)r_idx[b] * EDIM + i];
}

// ---------------- stage 3: metapath RGCNs (rows < NREG only) ------------------
__global__ void init_mp(int m, const int* __restrict__ eids) {
    int n = blockIdx.x;
    float* row = g_Y + (size_t)m * NREG * KMP + (size_t)n * KMP;
    const float4* er = (const float4*)(g_E + (size_t)eids[n] * EDIM);
    const float4 z = make_float4(0.f, 0.f, 0.f, 0.f);
    for (int j = threadIdx.x; j < KMP / 4; j += blockDim.x)
        ((float4*)row)[j] = (j < (KMP - EDIM) / 4) ? z : er[j - (KMP - EDIM) / 4];
    if (blockIdx.x == 0 && threadIdx.x < 2) g_w[threadIdx.x] = 0.f;
}

__global__ void scatter_mp(int m, const int* __restrict__ ei, const int* __restrict__ et,
                           const int* __restrict__ eids) {
    int w = (blockIdx.x * blockDim.x + threadIdx.x) >> 5;
    int lane = threadIdx.x & 31;
    if (w >= NMP_E) return;
    int dst = ei[NMP_E + w];
    if (dst >= NREG) return;  // output sliced [:NREG]
    int src = ei[w];
    int r = et[w];
    float4 v = *(const float4*)(g_E + (size_t)eids[src] * EDIM + lane * 4);
    red_add_v4(g_Y + (size_t)m * NREG * KMP + (size_t)dst * KMP + r * EDIM + lane * 4, v);
}

// ---------------- stage 4: semantic attention + head -------------------------
__global__ void attn(const float* __restrict__ w1, const float* __restrict__ b1,
                     const float* __restrict__ w2) {
    int n = blockIdx.x, m = blockIdx.y, tid = threadIdx.x;  // 128 threads
    __shared__ float z[HID];
    __shared__ float red[ATT];
    const float* zp = &g_sem[m][(size_t)n * HID];
    z[tid] = zp[tid];
    z[tid + 128] = zp[tid + 128];
    __syncthreads();
    float acc = b1[tid];
#pragma unroll 8
    for (int k = 0; k < HID; k++) acc = fmaf(z[k], w1[k * ATT + tid], acc);
    red[tid] = tanhf(acc) * w2[tid];
    __syncthreads();
    for (int s = 64; s > 0; s >>= 1) {
        if (tid < s) red[tid] += red[tid + s];
        __syncthreads();
    }
    if (tid == 0) atomicAdd(&g_w[m], red[0] * (1.0f / NREG));
}

__global__ void finalk(const float* __restrict__ predW, const float* __restrict__ predb,
                       float* __restrict__ out) {
    int n = blockIdx.x, tid = threadIdx.x;  // 128 threads
    __shared__ float h[HID];
    float w0 = g_w[0], w1v = g_w[1];
    float mx = fmaxf(w0, w1v);
    float e0 = expf(w0 - mx), e1 = expf(w1v - mx);
    float inv = 1.f / (e0 + e1);
    float b0 = e0 * inv, b1 = e1 * inv;
    h[tid] = b0 * g_sem[0][(size_t)n * HID + tid] + b1 * g_sem[1][(size_t)n * HID + tid];
    h[tid + 128] =
        b0 * g_sem[0][(size_t)n * HID + tid + 128] + b1 * g_sem[1][(size_t)n * HID + tid + 128];
    __syncthreads();
    float acc = predb[tid] + g_E[(size_t)n * EDIM + tid];
#pragma unroll 8
    for (int k = 0; k < HID; k++) acc = fmaf(h[k], predW[k * EDIM + tid], acc);
    out[(size_t)n * EDIM + tid] = acc;
}

// ---------------- launch ------------------------------------------------------
extern "C" void kernel_launch(void* const* d_in, const int* in_sizes, int n_in,
                              void* d_out, int out_size) {
    const float* E_weight = (const float*)d_in[0];
    const float* R_weight = (const float*)d_in[1];
    const float* rgcn_W = (const float*)d_in[2];
    const float* rgcn_Wroot = (const float*)d_in[3];
    const float* rgcn_b = (const float*)d_in[4];
    const float* mp0_W = (const float*)d_in[5];
    const float* mp0_Wroot = (const float*)d_in[6];
    const float* mp0_b = (const float*)d_in[7];
    const float* mp1_W = (const float*)d_in[8];
    const float* mp1_Wroot = (const float*)d_in[9];
    const float* mp1_b = (const float*)d_in[10];
    const float* sa_w1 = (const float*)d_in[11];
    const float* sa_b1 = (const float*)d_in[12];
    const float* sa_w2 = (const float*)d_in[13];
    const float* pred_W = (const float*)d_in[14];
    const float* pred_b = (const float*)d_in[15];
    const int* h_idx = (const int*)d_in[16];
    const int* r_idx = (const int*)d_in[17];
    const int* edge_index = (const int*)d_in[18];
    const int* edge_type = (const int*)d_in[19];
    const int* mp0_ei = (const int*)d_in[20];
    const int* mp0_et = (const int*)d_in[21];
    const int* mp0_eids = (const int*)d_in[22];
    const int* mp1_ei = (const int*)d_in[23];
    const int* mp1_et = (const int*)d_in[24];
    const int* mp1_eids = (const int*)d_in[25];
    float* out = (float*)d_out;  // [E_reg 2000*128 | pred 1024*100000]

    float *pY, *pE, *pET, *pBmain, *pBmp, *px, *psem;
    cudaGetSymbolAddress((void**)&pY, g_Y);
    cudaGetSymbolAddress((void**)&pE, g_E);
    cudaGetSymbolAddress((void**)&pET, g_ET);
    cudaGetSymbolAddress((void**)&pBmain, g_Bmain);
    cudaGetSymbolAddress((void**)&pBmp, g_Bmp);
    cudaGetSymbolAddress((void**)&px, g_x);
    cudaGetSymbolAddress((void**)&psem, g_sem);

    // --- main RGCN: Y = X @ [W0..W9 | Wroot]; scatter; tanh ---
    build_Bmain<<<(EDIM * NMAIN + 255) / 256, 256>>>(rgcn_W, rgcn_Wroot);
    gemm_tf32<<<dim3((NE + 127) / 128, NMAIN / 128), 256>>>(
        E_weight, EDIM, pBmain, NMAIN, nullptr, pY, NMAIN, NE, NMAIN, EDIM, 0);
    scatter_main<<<NKG / 8, 256>>>(edge_index, edge_type);
    tanh_root<<<(NE * (EDIM / 4) + 255) / 256, 256>>>(rgcn_b);

    // --- KGE pred = (E[h]*R[r]) @ E^T ---
    transposeE<<<dim3(NE / 32, EDIM / 32), dim3(32, 32)>>>();
    build_x<<<NB, EDIM>>>(h_idx, r_idx, R_weight);
    gemm_tf32<<<dim3(NB / 128, (NE + 127) / 128), 256>>>(
        px, EDIM, pET, NE, nullptr, out + NREG * EDIM, NE, NB, NE, EDIM, 0);

    // --- metapath RGCNs (rows < NREG) + relu ---
    init_mp<<<NREG, 128>>>(0, mp0_eids);
    init_mp<<<NREG, 128>>>(1, mp1_eids);
    cudaMemcpyAsync(pBmp, mp0_W, (size_t)NMP_REL * EDIM * HID * 4, cudaMemcpyDeviceToDevice);
    cudaMemcpyAsync(pBmp + NMP_REL * EDIM * HID, mp0_Wroot, (size_t)EDIM * HID * 4,
                    cudaMemcpyDeviceToDevice);
    cudaMemcpyAsync(pBmp + KMP * HID, mp1_W, (size_t)NMP_REL * EDIM * HID * 4,
                    cudaMemcpyDeviceToDevice);
    cudaMemcpyAsync(pBmp + KMP * HID + NMP_REL * EDIM * HID, mp1_Wroot, (size_t)EDIM * HID * 4,
                    cudaMemcpyDeviceToDevice);
    scatter_mp<<<NMP_E / 8, 256>>>(0, mp0_ei, mp0_et, mp0_eids);
    scatter_mp<<<NMP_E / 8, 256>>>(1, mp1_ei, mp1_et, mp1_eids);
    gemm_tf32<<<dim3((NREG + 127) / 128, HID / 128), 256>>>(
        pY, KMP, pBmp, HID, mp0_b, psem, HID, NREG, HID, KMP, 2);
    gemm_tf32<<<dim3((NREG + 127) / 128, HID / 128), 256>>>(
        pY + (size_t)NREG * KMP, KMP, pBmp + (size_t)KMP * HID, HID, mp1_b,
        psem + (size_t)NREG * HID, HID, NREG, HID, KMP, 2);

    // --- semantic attention + prediction head ---
    attn<<<dim3(NREG, 2), ATT>>>(sa_w1, sa_b1, sa_w2);
    finalk<<<NREG, EDIM>>>(pred_W, pred_b, out);
}

// round 4
// speedup vs baseline: 3.2785x; 1.5091x over previous
#include <cuda_runtime.h>
#include <cuda_fp16.h>
#include <math.h>
#include <stdint.h>

#define NE 100000
#define NR 10
#define EDIM 128
#define HID 256
#define NREG 2000
#define NKG 600000
#define NMP_REL 5
#define NMP_E 300000
#define NB 1024
#define ATT 128

#define NMAIN (NR * EDIM + EDIM)    /* 1408 */
#define KMP (NMP_REL * EDIM + EDIM) /* 768 */

// ---------------- scratch ----------------------------------------------------
__device__ float g_Y[(size_t)NE * NMAIN];  // GEMM1 out (fp32); root block = accumulator; reused for mp agg
__device__ float g_E[(size_t)NE * EDIM];
__device__ __half g_Eh[(size_t)NE * EDIM];   // E in fp16 (pred B operand)
__device__ __half g_Ah[(size_t)NE * EDIM];   // E_weight in fp16 (GEMM1 A operand)
__device__ __half g_BmainTh[NMAIN * EDIM];   // [n][k] fp16 (GEMM1 B operand)
__device__ float g_Bmp[2][KMP * HID];
__device__ __half g_xh[NB * EDIM];           // (E[h]*R[r]) fp16 (pred A operand)
__device__ float g_sem[2][NREG * HID];
__device__ float g_w[2];

// ---------------- primitives -------------------------------------------------
__device__ __forceinline__ void red_add_v4(float* addr, float4 v) {
    asm volatile("red.global.add.v4.f32 [%0], {%1, %2, %3, %4};"
                 :: "l"(addr), "f"(v.x), "f"(v.y), "f"(v.z), "f"(v.w) : "memory");
}
__device__ __forceinline__ void mma16816(float* c, const uint32_t* a, const uint32_t* b) {
    asm volatile(
        "mma.sync.aligned.m16n8k16.row.col.f32.f16.f16.f32 "
        "{%0,%1,%2,%3}, {%4,%5,%6,%7}, {%8,%9}, {%0,%1,%2,%3};"
        : "+f"(c[0]), "+f"(c[1]), "+f"(c[2]), "+f"(c[3])
        : "r"(a[0]), "r"(a[1]), "r"(a[2]), "r"(a[3]), "r"(b[0]), "r"(b[1]));
}
__device__ __forceinline__ float cvt_tf32(float x) {
    unsigned u;
    asm("cvt.rna.tf32.f32 %0, %1;" : "=r"(u) : "f"(x));
    return __uint_as_float(u);
}
__device__ __forceinline__ float4 cvt_tf32_4(float4 v) {
    return make_float4(cvt_tf32(v.x), cvt_tf32(v.y), cvt_tf32(v.z), cvt_tf32(v.w));
}
__device__ __forceinline__ void mma8(float* c, const unsigned* a, const unsigned* b) {
    asm volatile(
        "mma.sync.aligned.m16n8k8.row.col.f32.tf32.tf32.f32 "
        "{%0,%1,%2,%3}, {%4,%5,%6,%7}, {%8,%9}, {%0,%1,%2,%3};"
        : "+f"(c[0]), "+f"(c[1]), "+f"(c[2]), "+f"(c[3])
        : "r"(a[0]), "r"(a[1]), "r"(a[2]), "r"(a[3]), "r"(b[0]), "r"(b[1]));
}

// ---------------- fp16 K=128-resident GEMM: C = A[M,128] @ Bt[N,128]^T --------
// 256 thr, 8 warps (4x2), warp tile 32x64, whole K in SMEM, fp32 out
#define SPAD 136  /* 128 + 8 halves pad: (4g+t) bank mapping conflict-free */
__global__ __launch_bounds__(256, 2)
void gemm_f16_k128(const __half* __restrict__ A, const __half* __restrict__ Bt,
                   float* __restrict__ C, int M, int N, size_t ldc) {
    extern __shared__ __half sm[];
    __half(*As)[SPAD] = (__half(*)[SPAD])sm;
    __half(*Bs)[SPAD] = (__half(*)[SPAD])(sm + 128 * SPAD);
    const int tid = threadIdx.x, lane = tid & 31, warp = tid >> 5;
    const int g = lane >> 2, t = lane & 3;
    const int wm = (warp >> 1) * 32, wn = (warp & 1) * 64;
    const int m0 = blockIdx.x * 128, n0 = blockIdx.y * 128;

    const uint4 z = make_uint4(0, 0, 0, 0);
#pragma unroll
    for (int l = 0; l < 8; l++) {               // 2048 uint4 (8 halves) total
        int e = l * 256 + tid;
        int r = e >> 4, c8 = (e & 15) * 8;
        uint4 va = z, vb = z;
        if (m0 + r < M) va = *(const uint4*)&A[(size_t)(m0 + r) * 128 + c8];
        if (n0 + r < N) vb = *(const uint4*)&Bt[(size_t)(n0 + r) * 128 + c8];
        *(uint4*)&As[r][c8] = va;
        *(uint4*)&Bs[r][c8] = vb;
    }
    __syncthreads();

    float c[2][8][4];
#pragma unroll
    for (int i = 0; i < 2; i++)
#pragma unroll
        for (int j = 0; j < 8; j++)
#pragma unroll
            for (int l = 0; l < 4; l++) c[i][j][l] = 0.f;

#pragma unroll
    for (int kb = 0; kb < 128; kb += 16) {
        uint32_t a[2][4], b[8][2];
#pragma unroll
        for (int mt = 0; mt < 2; mt++) {
            int row = wm + mt * 16 + g;
            a[mt][0] = *(const uint32_t*)&As[row][kb + 2 * t];
            a[mt][1] = *(const uint32_t*)&As[row + 8][kb + 2 * t];
            a[mt][2] = *(const uint32_t*)&As[row][kb + 2 * t + 8];
            a[mt][3] = *(const uint32_t*)&As[row + 8][kb + 2 * t + 8];
        }
#pragma unroll
        for (int nt = 0; nt < 8; nt++) {
            int col = wn + nt * 8 + g;
            b[nt][0] = *(const uint32_t*)&Bs[col][kb + 2 * t];
            b[nt][1] = *(const uint32_t*)&Bs[col][kb + 2 * t + 8];
        }
#pragma unroll
        for (int mt = 0; mt < 2; mt++)
#pragma unroll
            for (int nt = 0; nt < 8; nt++) mma16816(c[mt][nt], a[mt], b[nt]);
    }

#pragma unroll
    for (int mt = 0; mt < 2; mt++) {
#pragma unroll
        for (int h = 0; h < 2; h++) {
            int row = m0 + wm + mt * 16 + g + h * 8;
            if (row >= M) continue;
#pragma unroll
            for (int nt = 0; nt < 8; nt++) {
                int col = n0 + wn + nt * 8 + 2 * t;
                if (col >= N) continue;  // N even -> col+1 < N too
                *(float2*)&C[(size_t)row * ldc + col] =
                    make_float2(c[mt][nt][h * 2 + 0], c[mt][nt][h * 2 + 1]);
            }
        }
    }
}

// ---------------- tf32 mma GEMM (metapath GEMMs, K=768) ----------------------
__global__ __launch_bounds__(256)
void gemm_tf32(const float* __restrict__ A, int lda, const float* __restrict__ B, int ldb,
               const float* __restrict__ bias, float* __restrict__ C, int ldc,
               int M, int N, int K, int act) {
    __shared__ float As[2][128][20];
    __shared__ float Bs[2][16][136];
    const int bm = blockIdx.x * 128;
    const int bn = blockIdx.y * 128;
    const int tid = threadIdx.x;
    const int lane = tid & 31;
    const int warp = tid >> 5;
    const int g = lane >> 2, t = lane & 3;
    const int wm = (warp >> 1) * 32;
    const int wn = (warp & 1) * 64;

    float c[2][8][4];
#pragma unroll
    for (int i = 0; i < 2; i++)
#pragma unroll
        for (int j = 0; j < 8; j++)
#pragma unroll
            for (int l = 0; l < 4; l++) c[i][j][l] = 0.f;

    float4 ar[2], br[2];
    const float4 z4 = make_float4(0.f, 0.f, 0.f, 0.f);

    auto ldg = [&](int k0) {
#pragma unroll
        for (int l = 0; l < 2; l++) {
            int e = tid + l * 256;
            int m = e >> 2, k4 = (e & 3) * 4;
            int gm = bm + m;
            ar[l] = (gm < M) ? *(const float4*)&A[(size_t)gm * lda + k0 + k4] : z4;
            int kr = e >> 5, nc = (e & 31) * 4;
            int gc = bn + nc;
            br[l] = (gc < N) ? *(const float4*)&B[(size_t)(k0 + kr) * ldb + gc] : z4;
        }
    };
    auto sts = [&](int buf) {
#pragma unroll
        for (int l = 0; l < 2; l++) {
            int e = tid + l * 256;
            int m = e >> 2, k4 = (e & 3) * 4;
            float4 a4 = cvt_tf32_4(ar[l]);
            As[buf][m][k4 + 0] = a4.x;
            As[buf][m][k4 + 1] = a4.y;
            As[buf][m][k4 + 2] = a4.z;
            As[buf][m][k4 + 3] = a4.w;
            int kr = e >> 5, nc = (e & 31) * 4;
            *(float4*)&Bs[buf][kr][nc] = cvt_tf32_4(br[l]);
        }
    };
    auto compute = [&](int buf) {
#pragma unroll
        for (int kk = 0; kk < 2; kk++) {
            const int kb = kk * 8;
            unsigned a[2][4], b[8][2];
#pragma unroll
            for (int mt = 0; mt < 2; mt++) {
                int row = wm + mt * 16 + g;
                a[mt][0] = __float_as_uint(As[buf][row][kb + t]);
                a[mt][1] = __float_as_uint(As[buf][row + 8][kb + t]);
                a[mt][2] = __float_as_uint(As[buf][row][kb + t + 4]);
                a[mt][3] = __float_as_uint(As[buf][row + 8][kb + t + 4]);
            }
#pragma unroll
            for (int nt = 0; nt < 8; nt++) {
                int col = wn + nt * 8 + g;
                b[nt][0] = __float_as_uint(Bs[buf][kb + t][col]);
                b[nt][1] = __float_as_uint(Bs[buf][kb + t + 4][col]);
            }
#pragma unroll
            for (int mt = 0; mt < 2; mt++)
#pragma unroll
                for (int nt = 0; nt < 8; nt++) mma8(c[mt][nt], a[mt], b[nt]);
        }
    };

    const int iters = K >> 4;
    ldg(0);
    sts(0);
    __syncthreads();
    for (int it = 0; it < iters; it++) {
        int buf = it & 1;
        if (it + 1 < iters) ldg((it + 1) << 4);
        compute(buf);
        if (it + 1 < iters) sts(buf ^ 1);
        __syncthreads();
    }

#pragma unroll
    for (int mt = 0; mt < 2; mt++) {
#pragma unroll
        for (int h = 0; h < 2; h++) {
            int row = bm + wm + mt * 16 + g + h * 8;
            if (row >= M) continue;
#pragma unroll
            for (int nt = 0; nt < 8; nt++) {
                int col = bn + wn + nt * 8 + 2 * t;
                if (col >= N) continue;
                float v0 = c[mt][nt][h * 2 + 0];
                float v1 = c[mt][nt][h * 2 + 1];
                if (bias) { v0 += bias[col]; v1 += bias[col + 1]; }
                if (act == 2) { v0 = fmaxf(v0, 0.f); v1 = fmaxf(v1, 0.f); }
                *(float2*)&C[(size_t)row * ldc + col] = make_float2(v0, v1);
            }
        }
    }
}

// ---------------- conversions / stage 1 --------------------------------------
__global__ void f2h(const float* __restrict__ src, __half* __restrict__ dst, int n4) {
    int i = blockIdx.x * blockDim.x + threadIdx.x;
    if (i >= n4) return;
    float4 v = ((const float4*)src)[i];
    ((__half2*)dst)[2 * i + 0] = __floats2half2_rn(v.x, v.y);
    ((__half2*)dst)[2 * i + 1] = __floats2half2_rn(v.z, v.w);
}

__global__ void build_BmainTh(const float* __restrict__ W, const float* __restrict__ Wroot) {
    int i = blockIdx.x * blockDim.x + threadIdx.x;  // over 1408*128
    if (i >= NMAIN * EDIM) return;
    int n = i >> 7, k = i & 127;
    int r = n >> 7, o = n & 127;
    float v = (r < NR) ? W[((size_t)r * EDIM + k) * EDIM + o] : Wroot[(size_t)k * EDIM + o];
    g_BmainTh[i] = __float2half_rn(v);
}

__global__ void scatter_main(const int* __restrict__ ei, const int* __restrict__ et) {
    int w = (blockIdx.x * blockDim.x + threadIdx.x) >> 5;
    int lane = threadIdx.x & 31;
    if (w >= NKG) return;
    int src = ei[w], dst = ei[NKG + w], r = et[w];
    float4 v = *(const float4*)(g_Y + (size_t)src * NMAIN + r * EDIM + lane * 4);
    red_add_v4(g_Y + (size_t)dst * NMAIN + NR * EDIM + lane * 4, v);
}

__global__ void tanh_root(const float* __restrict__ b) {
    int i = blockIdx.x * blockDim.x + threadIdx.x;  // float4 units
    if (i >= NE * (EDIM / 4)) return;
    int n = i >> 5, j = (i & 31) * 4;
    float4 v = *(const float4*)&g_Y[(size_t)n * NMAIN + NR * EDIM + j];
    float4 bb = *(const float4*)&b[j];
    v.x = tanhf(v.x + bb.x);
    v.y = tanhf(v.y + bb.y);
    v.z = tanhf(v.z + bb.z);
    v.w = tanhf(v.w + bb.w);
    *(float4*)&g_E[(size_t)n * EDIM + j] = v;
    __half2* eh = (__half2*)&g_Eh[(size_t)n * EDIM + j];
    eh[0] = __floats2half2_rn(v.x, v.y);
    eh[1] = __floats2half2_rn(v.z, v.w);
}

// ---------------- stage 2: KGE scoring ---------------------------------------
__global__ void build_x(const int* __restrict__ h_idx, const int* __restrict__ r_idx,
                        const float* __restrict__ R) {
    int b = blockIdx.x, i = threadIdx.x;
    float v = g_E[(size_t)h_idx[b] * EDIM + i] * R[(size_t)r_idx[b] * EDIM + i];
    g_xh[b * EDIM + i] = __float2half_rn(v);
}

// ---------------- stage 3: metapath RGCNs ------------------------------------
__global__ void init_mp(int m, const int* __restrict__ eids) {
    int n = blockIdx.x;
    float* row = g_Y + (size_t)m * NREG * KMP + (size_t)n * KMP;
    const float4* er = (const float4*)(g_E + (size_t)eids[n] * EDIM);
    const float4 z = make_float4(0.f, 0.f, 0.f, 0.f);
    for (int j = threadIdx.x; j < KMP / 4; j += blockDim.x)
        ((float4*)row)[j] = (j < (KMP - EDIM) / 4) ? z : er[j - (KMP - EDIM) / 4];
    if (blockIdx.x == 0 && threadIdx.x < 2) g_w[threadIdx.x] = 0.f;
}

__global__ void scatter_mp(int m, const int* __restrict__ ei, const int* __restrict__ et,
                           const int* __restrict__ eids) {
    int w = (blockIdx.x * blockDim.x + threadIdx.x) >> 5;
    int lane = threadIdx.x & 31;
    if (w >= NMP_E) return;
    int dst = ei[NMP_E + w];
    if (dst >= NREG) return;  // output sliced [:NREG]
    int src = ei[w];
    int r = et[w];
    float4 v = *(const float4*)(g_E + (size_t)eids[src] * EDIM + lane * 4);
    red_add_v4(g_Y + (size_t)m * NREG * KMP + (size_t)dst * KMP + r * EDIM + lane * 4, v);
}

// ---------------- stage 4: semantic attention + head -------------------------
__global__ void attn(const float* __restrict__ w1, const float* __restrict__ b1,
                     const float* __restrict__ w2) {
    int n = blockIdx.x, m = blockIdx.y, tid = threadIdx.x;
    __shared__ float z[HID];
    __shared__ float red[ATT];
    const float* zp = &g_sem[m][(size_t)n * HID];
    z[tid] = zp[tid];
    z[tid + 128] = zp[tid + 128];
    __syncthreads();
    float acc = b1[tid];
#pragma unroll 8
    for (int k = 0; k < HID; k++) acc = fmaf(z[k], w1[k * ATT + tid], acc);
    red[tid] = tanhf(acc) * w2[tid];
    __syncthreads();
    for (int s = 64; s > 0; s >>= 1) {
        if (tid < s) red[tid] += red[tid + s];
        __syncthreads();
    }
    if (tid == 0) atomicAdd(&g_w[m], red[0] * (1.0f / NREG));
}

__global__ void finalk(const float* __restrict__ predW, const float* __restrict__ predb,
                       float* __restrict__ out) {
    int n = blockIdx.x, tid = threadIdx.x;
    __shared__ float h[HID];
    float w0 = g_w[0], w1v = g_w[1];
    float mx = fmaxf(w0, w1v);
    float e0 = expf(w0 - mx), e1 = expf(w1v - mx);
    float inv = 1.f / (e0 + e1);
    float b0 = e0 * inv, b1 = e1 * inv;
    h[tid] = b0 * g_sem[0][(size_t)n * HID + tid] + b1 * g_sem[1][(size_t)n * HID + tid];
    h[tid + 128] =
        b0 * g_sem[0][(size_t)n * HID + tid + 128] + b1 * g_sem[1][(size_t)n * HID + tid + 128];
    __syncthreads();
    float acc = predb[tid] + g_E[(size_t)n * EDIM + tid];
#pragma unroll 8
    for (int k = 0; k < HID; k++) acc = fmaf(h[k], predW[k * EDIM + tid], acc);
    out[(size_t)n * EDIM + tid] = acc;
}

// ---------------- launch ------------------------------------------------------
extern "C" void kernel_launch(void* const* d_in, const int* in_sizes, int n_in,
                              void* d_out, int out_size) {
    const float* E_weight = (const float*)d_in[0];
    const float* R_weight = (const float*)d_in[1];
    const float* rgcn_W = (const float*)d_in[2];
    const float* rgcn_Wroot = (const float*)d_in[3];
    const float* rgcn_b = (const float*)d_in[4];
    const float* mp0_W = (const float*)d_in[5];
    const float* mp0_Wroot = (const float*)d_in[6];
    const float* mp0_b = (const float*)d_in[7];
    const float* mp1_W = (const float*)d_in[8];
    const float* mp1_Wroot = (const float*)d_in[9];
    const float* mp1_b = (const float*)d_in[10];
    const float* sa_w1 = (const float*)d_in[11];
    const float* sa_b1 = (const float*)d_in[12];
    const float* sa_w2 = (const float*)d_in[13];
    const float* pred_W = (const float*)d_in[14];
    const float* pred_b = (const float*)d_in[15];
    const int* h_idx = (const int*)d_in[16];
    const int* r_idx = (const int*)d_in[17];
    const int* edge_index = (const int*)d_in[18];
    const int* edge_type = (const int*)d_in[19];
    const int* mp0_ei = (const int*)d_in[20];
    const int* mp0_et = (const int*)d_in[21];
    const int* mp0_eids = (const int*)d_in[22];
    const int* mp1_ei = (const int*)d_in[23];
    const int* mp1_et = (const int*)d_in[24];
    const int* mp1_eids = (const int*)d_in[25];
    float* out = (float*)d_out;  // [E_reg 2000*128 | pred 1024*100000]

    float *pY, *pE, *pBmp, *psem;
    __half *pAh, *pEh, *pBmTh, *pxh;
    cudaGetSymbolAddress((void**)&pY, g_Y);
    cudaGetSymbolAddress((void**)&pE, g_E);
    cudaGetSymbolAddress((void**)&pBmp, g_Bmp);
    cudaGetSymbolAddress((void**)&psem, g_sem);
    cudaGetSymbolAddress((void**)&pAh, g_Ah);
    cudaGetSymbolAddress((void**)&pEh, g_Eh);
    cudaGetSymbolAddress((void**)&pBmTh, g_BmainTh);
    cudaGetSymbolAddress((void**)&pxh, g_xh);

    const int SMEM_F16 = 2 * 128 * SPAD * (int)sizeof(__half);  // 69,632 B
    cudaFuncSetAttribute(gemm_f16_k128, cudaFuncAttributeMaxDynamicSharedMemorySize, SMEM_F16);

    // --- main RGCN: Y = Xh @ BmainTh^T ; scatter messages into root block; tanh ---
    f2h<<<(NE * EDIM / 4 + 255) / 256, 256>>>(E_weight, pAh, NE * EDIM / 4);
    build_BmainTh<<<(NMAIN * EDIM + 255) / 256, 256>>>(rgcn_W, rgcn_Wroot);
    gemm_f16_k128<<<dim3((NE + 127) / 128, NMAIN / 128), 256, SMEM_F16>>>(
        pAh, pBmTh, pY, NE, NMAIN, NMAIN);
    scatter_main<<<NKG / 8, 256>>>(edge_index, edge_type);
    tanh_root<<<(NE * (EDIM / 4) + 255) / 256, 256>>>(rgcn_b);

    // --- KGE pred = (E[h]*R[r]) @ E^T  (Eh is directly the [N,K] B operand) ---
    build_x<<<NB, EDIM>>>(h_idx, r_idx, R_weight);
    gemm_f16_k128<<<dim3(NB / 128, (NE + 127) / 128), 256, SMEM_F16>>>(
        pxh, pEh, out + NREG * EDIM, NB, NE, NE);

    // --- metapath RGCNs (rows < NREG) + relu ---
    init_mp<<<NREG, 128>>>(0, mp0_eids);
    init_mp<<<NREG, 128>>>(1, mp1_eids);
    cudaMemcpyAsync(pBmp, mp0_W, (size_t)NMP_REL * EDIM * HID * 4, cudaMemcpyDeviceToDevice);
    cudaMemcpyAsync(pBmp + NMP_REL * EDIM * HID, mp0_Wroot, (size_t)EDIM * HID * 4,
                    cudaMemcpyDeviceToDevice);
    cudaMemcpyAsync(pBmp + KMP * HID, mp1_W, (size_t)NMP_REL * EDIM * HID * 4,
                    cudaMemcpyDeviceToDevice);
    cudaMemcpyAsync(pBmp + KMP * HID + NMP_REL * EDIM * HID, mp1_Wroot, (size_t)EDIM * HID * 4,
                    cudaMemcpyDeviceToDevice);
    scatter_mp<<<NMP_E / 8, 256>>>(0, mp0_ei, mp0_et, mp0_eids);
    scatter_mp<<<NMP_E / 8, 256>>>(1, mp1_ei, mp1_et, mp1_eids);
    gemm_tf32<<<dim3((NREG + 127) / 128, HID / 128), 256>>>(
        pY, KMP, pBmp, HID, mp0_b, psem, HID, NREG, HID, KMP, 2);
    gemm_tf32<<<dim3((NREG + 127) / 128, HID / 128), 256>>>(
        pY + (size_t)NREG * KMP, KMP, pBmp + (size_t)KMP * HID, HID, mp1_b,
        psem + (size_t)NREG * HID, HID, NREG, HID, KMP, 2);

    // --- semantic attention + prediction head ---
    attn<<<dim3(NREG, 2), ATT>>>(sa_w1, sa_b1, sa_w2);
    finalk<<<NREG, EDIM>>>(pred_W, pred_b, out);
}